// round 15
// baseline (speedup 1.0000x reference)
#include <cuda_runtime.h>
#include <math.h>

#define NQ       22
#define NSTATES  (1u << NQ)
#define MASK22   (NSTATES - 1u)

// Ping-pong scratch (sanctioned __device__ globals; no allocation).
__device__ float2 g_A[NSTATES];
__device__ float2 g_B[NSTATES];

// Inverse of the CNOT-chain permutation pxor (y_k = x_0^..^x_k):
// pinv(y) = (y ^ (y<<1)) & mask. Gather form: w[y] = u[pinv(y)].
__device__ __forceinline__ unsigned pinv22(unsigned y) {
    return (y ^ (y << 1)) & MASK22;
}

// Swizzle: fold v bits [4:8) AND [8:12) into the low nibble. Bank bit j of an
// 8B bank = v_j ^ v_{j+4} ^ v_{j+8}; every ownership pattern below assigns its
// 4 half-warp lane bits to 4 distinct bank bits -> conflict-free LDS.64/STS.64.
__device__ __forceinline__ unsigned sw3(unsigned v) {
    return v ^ ((v >> 4) & 15u) ^ ((v >> 8) & 15u);
}

// Up to 3 RY butterfly stages on 8 register-resident amplitudes.
// Register-index bit s <-> stage s; MASK selects active stages.
// RY: new0 = c*a0 - s*a1 ; new1 = s*a0 + c*a1 (same coeffs for re & im).
template<int MASK>
__device__ __forceinline__ void group3(float2 (&r)[8],
                                       const float* __restrict__ CB,
                                       const float* __restrict__ SB) {
#pragma unroll
    for (int s = 0; s < 3; s++) {
        if (((MASK >> s) & 1) == 0) continue;
        const float c  = CB[s];
        const float sn = SB[s];
#pragma unroll
        for (int p = 0; p < 4; p++) {
            const int m  = ((p >> s) << (s + 1)) | (p & ((1 << s) - 1));
            const int m1 = m | (1 << s);
            const float2 a0 = r[m], a1 = r[m1];
            r[m]  = make_float2(c  * a0.x - sn * a1.x, c  * a0.y - sn * a1.y);
            r[m1] = make_float2(sn * a0.x + c  * a1.x, sn * a0.y + c  * a1.y);
        }
    }
}

// Ownership patterns (v = 12-bit local index, t = 9-bit thread id, i = 3-bit
// register index). Each pattern's reg bits are a distinct v-bit triple; lane
// bits map injectively to bank bits under sw3.
//   P_LD (= load/store-side of stages 9..11): v = (i<<9) | t
//   P1   (stages 0..2):                       v = (t<<3) | i
//   P2   (stages 3..5):  v = (t&7) | (i<<3) | (((t>>4)&1)<<6)
//                            | (((t>>3)&1)<<7) | ((t>>5)<<8)
//   P3   (stages 6..8):  v = (t&15) | (((t>>4)&3)<<4) | (i<<6) | ((t>>6)<<9)
__device__ __forceinline__ unsigned vP2(unsigned t, unsigned i) {
    return (t & 7u) | (i << 3) | (((t >> 4) & 1u) << 6)
         | (((t >> 3) & 1u) << 7) | ((t >> 5) << 8);
}
__device__ __forceinline__ unsigned vP3(unsigned t, unsigned i) {
    return (t & 15u) | (((t >> 4) & 3u) << 4) | (i << 6) | ((t >> 6) << 9);
}

// Global index for local v:
//   LOW:  g = blk<<12 | v                  (v bits 0..11 = qubits 0..11)
//   HIGH: g = (v>>2)<<12 | blk<<2 | (v&3)  (v bits 2..11 = qubits 12..21;
//                                           v bits 0,1 ride along, identity)
template<bool HIGH>
__device__ __forceinline__ unsigned gmap(unsigned blk, unsigned v) {
    return HIGH ? (((v >> 2) << 12) | (blk << 2) | (v & 3u))
                : ((blk << 12) | v);
}

// One full-state pass: 1024 blocks x 512 threads, 4096 amps/block, 8/thread.
// GATHER: load src[pinv22(g)] (folds the preceding CNOT-chain permutation).
// IN_PLANAR: load from planar sre/sim. OUT_REAL: store real parts to outp[g]
// (+ imag plane only if write_imag, i.e. the buffer holds 2*NSTATES floats).
template<bool HIGH, bool GATHER, bool IN_PLANAR, bool OUT_REAL>
__global__ void __launch_bounds__(512, 2)
vqc_fused(const float* __restrict__ sre, const float* __restrict__ sim,
          float* __restrict__ outp, int write_imag, int srcsel, int dstsel,
          const float* __restrict__ params, int pbase)
{
    __shared__ float2 S[4096];
    __shared__ float CB[12];
    __shared__ float SB[12];

    const float2* __restrict__ src = (srcsel == 1) ? g_A : g_B;
    float2* __restrict__ dst       = (dstsel == 1) ? g_A : g_B;

    const unsigned t   = threadIdx.x;   // 512 threads
    const unsigned blk = blockIdx.x;    // 1024 blocks

    // Rotation coefficients per v-bit. HIGH: v bits 0,1 are identity;
    // v bit k (k>=2) <-> qubit k+10 <-> params[pbase + k - 2].
    if (t < 12) {
        float c = 1.f, s = 0.f;
        if (!HIGH || t >= 2) {
            const float a = params[pbase + (HIGH ? (int)t - 2 : (int)t)];
            sincosf(0.5f * a, &s, &c);
        }
        CB[t] = c; SB[t] = s;
    }

    float2 r[8];

    // ---- Load (pattern P_LD: v = (i<<9)|t), stages 9..11 in registers ----
#pragma unroll
    for (int i = 0; i < 8; i++) {
        const unsigned g = gmap<HIGH>(blk, ((unsigned)i << 9) | t);
        if (IN_PLANAR) r[i] = make_float2(sre[g], sim[g]);
        else           r[i] = src[GATHER ? pinv22(g) : g];
    }
    __syncthreads();                    // CB/SB visible
    group3<7>(r, CB + 9, SB + 9);       // stages 9,10,11 (active in LOW & HIGH)
#pragma unroll
    for (int i = 0; i < 8; i++) S[sw3(((unsigned)i << 9) | t)] = r[i];
    __syncthreads();

    // ---- P1 (reg = v bits 0..2): stages 0..2 ----
#pragma unroll
    for (int i = 0; i < 8; i++) r[i] = S[sw3((t << 3) | (unsigned)i)];
    if (HIGH) group3<4>(r, CB, SB);     // bits 0,1 identity
    else      group3<7>(r, CB, SB);
#pragma unroll
    for (int i = 0; i < 8; i++) S[sw3((t << 3) | (unsigned)i)] = r[i];
    __syncthreads();

    // ---- P2 (reg = v bits 3..5): stages 3..5 ----
#pragma unroll
    for (int i = 0; i < 8; i++) r[i] = S[sw3(vP2(t, (unsigned)i))];
    group3<7>(r, CB + 3, SB + 3);
#pragma unroll
    for (int i = 0; i < 8; i++) S[sw3(vP2(t, (unsigned)i))] = r[i];
    __syncthreads();

    // ---- P3 (reg = v bits 6..8): stages 6..8, then store from registers ----
#pragma unroll
    for (int i = 0; i < 8; i++) r[i] = S[sw3(vP3(t, (unsigned)i))];
    group3<7>(r, CB + 6, SB + 6);

#pragma unroll
    for (int i = 0; i < 8; i++) {
        const unsigned g = gmap<HIGH>(blk, vP3(t, (unsigned)i));
        if (OUT_REAL) {
            outp[g] = r[i].x;                              // real plane
            if (write_imag) outp[g + NSTATES] = r[i].y;
        } else {
            dst[g] = r[i];
        }
    }
}

extern "C" void kernel_launch(void* const* d_in, const int* in_sizes, int n_in,
                              void* d_out, int out_size) {
    if (n_in < 3) return;
    // Binding (proven round 9): params = smallest input; remaining two in
    // original order are state_real, state_imag. Never index past n_in.
    int pi = 0;
    for (int i = 1; i < n_in && i < 8; i++)
        if (in_sizes[i] < in_sizes[pi]) pi = i;
    int si0 = -1, si1 = -1;
    for (int i = 0; i < n_in && i < 8; i++) {
        if (i == pi) continue;
        if (si0 < 0) si0 = i; else if (si1 < 0) si1 = i;
    }
    if (si0 < 0 || si1 < 0) return;
    if ((unsigned)in_sizes[si0] < NSTATES || (unsigned)in_sizes[si1] < NSTATES)
        return;
    // Output contract (proven rounds 9+11/12): out_size = NSTATES float32
    // components = the REAL parts of the final state.
    if ((unsigned)out_size < NSTATES) return;
    const int write_imag = ((long long)out_size >= 2LL * NSTATES) ? 1 : 0;

    const float* params = (const float*)d_in[pi];
    const float* sre    = (const float*)d_in[si0];
    const float* sim    = (const float*)d_in[si1];
    float*       out    = (float*)d_out;

    const dim3 grid(1024), block(512);

    // L0: LOW (qubits 0..11) then HIGH (12..21).
    vqc_fused<false, false, true,  false><<<grid, block>>>(sre, sim, nullptr, 0, 0, 1, params, 0);
    vqc_fused<true,  false, false, false><<<grid, block>>>(nullptr, nullptr, nullptr, 0, 1, 2, params, 12);
    // L1: LOW with gathered CNOT-chain perm, then HIGH.
    vqc_fused<false, true,  false, false><<<grid, block>>>(nullptr, nullptr, nullptr, 0, 2, 1, params, 22);
    vqc_fused<true,  false, false, false><<<grid, block>>>(nullptr, nullptr, nullptr, 0, 1, 2, params, 34);
    // L2 (stages commute): HIGH with gathered perm, then LOW storing real parts.
    vqc_fused<true,  true,  false, false><<<grid, block>>>(nullptr, nullptr, nullptr, 0, 2, 1, params, 56);
    vqc_fused<false, false, false, true ><<<grid, block>>>(nullptr, nullptr, out, write_imag, 1, 0, params, 44);
}

// round 16
// speedup vs baseline: 1.1885x; 1.1885x over previous
#include <cuda_runtime.h>
#include <math.h>

#define NQ       22
#define NSTATES  (1u << NQ)
#define MASK22   (NSTATES - 1u)

// Ping-pong scratch (sanctioned __device__ globals; no allocation).
__device__ float2 g_A[NSTATES];
__device__ float2 g_B[NSTATES];

// Inverse of the CNOT-chain permutation pxor (y_k = x_0^..^x_k):
// pinv(y) = (y ^ (y<<1)) & mask. Gather form: w[y] = u[pinv(y)].
__device__ __forceinline__ unsigned pinv22(unsigned y) {
    return (y ^ (y << 1)) & MASK22;
}

// Swizzle: fold v bits [4:8) and [8:12) into the low nibble. 8B-bank index =
// low nibble of sw3(v); each pattern below varies 4 distinct v-bit positions
// across a half-warp -> bijective bank map -> conflict-free LDS.64/STS.64.
__device__ __forceinline__ unsigned sw3(unsigned v) {
    return v ^ ((v >> 4) & 15u) ^ ((v >> 8) & 15u);
}

// 4 RY butterfly stages on 16 register-resident amplitudes.
// Register-index bit s <-> stage s; MASK selects active stages.
// RY: new0 = c*a0 - s*a1 ; new1 = s*a0 + c*a1 (same coeffs for re & im).
template<int MASK>
__device__ __forceinline__ void group4(float2 (&r)[16],
                                       const float* __restrict__ CB,
                                       const float* __restrict__ SB) {
#pragma unroll
    for (int s = 0; s < 4; s++) {
        if (((MASK >> s) & 1) == 0) continue;
        const float c  = CB[s];
        const float sn = SB[s];
#pragma unroll
        for (int p = 0; p < 8; p++) {
            const int m  = ((p >> s) << (s + 1)) | (p & ((1 << s) - 1));
            const int m1 = m | (1 << s);
            const float2 a0 = r[m], a1 = r[m1];
            r[m]  = make_float2(c  * a0.x - sn * a1.x, c  * a0.y - sn * a1.y);
            r[m1] = make_float2(sn * a0.x + c  * a1.x, sn * a0.y + c  * a1.y);
        }
    }
}

// Ownership patterns (v = 12-bit local index, t = 8-bit thread id, i = 4-bit
// register index). Reg bits per pattern are a distinct v-bit quad:
//   P_LD (load/store side): v = (i<<8) | t          regs = v8..11
//   P1:                     v = (t<<4) | i          regs = v0..3
//   P2:                     v = (t&15)|(i<<4)|((t>>4)<<8)   regs = v4..7
__device__ __forceinline__ unsigned vQ2(unsigned t, unsigned i) {
    return (t & 15u) | (i << 4) | ((t >> 4) << 8);
}

// Global index for local v:
//   LOW:  g = blk<<12 | v                  (v bits 0..11 = qubits 0..11)
//   HIGH: g = (v>>2)<<12 | blk<<2 | (v&3)  (v bits 2..11 = qubits 12..21;
//                                           v bits 0,1 ride along, identity)
template<bool HIGH>
__device__ __forceinline__ unsigned gmap(unsigned blk, unsigned v) {
    return HIGH ? (((v >> 2) << 12) | (blk << 2) | (v & 3u))
                : ((blk << 12) | v);
}

// One full-state pass: 1024 blocks x 256 threads, 4096 amps/block, 16/thread.
// 2 smem round trips: load->(stages 8..11)->S ; S->(0..3)->S ; S->(4..7)->store.
// GATHER: load src[pinv22(g)]. IN_PLANAR: load planar sre/sim.
// OUT_REAL: store real parts to outp[g] (+ imag plane iff write_imag).
template<bool HIGH, bool GATHER, bool IN_PLANAR, bool OUT_REAL>
__global__ void __launch_bounds__(256)
vqc_pass16(const float* __restrict__ sre, const float* __restrict__ sim,
           float* __restrict__ outp, int write_imag, int srcsel, int dstsel,
           const float* __restrict__ params, int pbase)
{
    __shared__ float2 S[4096];
    __shared__ float CB[12];
    __shared__ float SB[12];

    const float2* __restrict__ src = (srcsel == 1) ? g_A : g_B;
    float2* __restrict__ dst       = (dstsel == 1) ? g_A : g_B;

    const unsigned t   = threadIdx.x;   // 256 threads
    const unsigned blk = blockIdx.x;    // 1024 blocks

    // Rotation coefficients per v-bit. HIGH: v bits 0,1 are identity;
    // v bit k (k>=2) <-> qubit k+10 <-> params[pbase + k - 2].
    if (t < 12) {
        float c = 1.f, s = 0.f;
        if (!HIGH || t >= 2) {
            const float a = params[pbase + (HIGH ? (int)t - 2 : (int)t)];
            sincosf(0.5f * a, &s, &c);
        }
        CB[t] = c; SB[t] = s;
    }

    float2 r[16];

    // ---- Load (P_LD: v = (i<<8)|t); src bytes are dead after this single
    // read -> evict-first (__ldcs) frees L2 for the live stream. ----
#pragma unroll
    for (int i = 0; i < 16; i++) {
        const unsigned g = gmap<HIGH>(blk, ((unsigned)i << 8) | t);
        if (IN_PLANAR) {
            r[i] = make_float2(__ldcs(sre + g), __ldcs(sim + g));
        } else {
            const unsigned idx = GATHER ? pinv22(g) : g;
            r[i] = __ldcs(src + idx);
        }
    }
    __syncthreads();                    // CB/SB visible
    group4<0xF>(r, CB + 8, SB + 8);     // stages 8..11 (active in LOW & HIGH)
#pragma unroll
    for (int i = 0; i < 16; i++) S[sw3(((unsigned)i << 8) | t)] = r[i];
    __syncthreads();

    // ---- P1 (regs = v bits 0..3): stages 0..3 ----
#pragma unroll
    for (int i = 0; i < 16; i++) r[i] = S[sw3((t << 4) | (unsigned)i)];
    if (HIGH) group4<0xC>(r, CB, SB);   // bits 0,1 identity
    else      group4<0xF>(r, CB, SB);
#pragma unroll
    for (int i = 0; i < 16; i++) S[sw3((t << 4) | (unsigned)i)] = r[i];
    __syncthreads();

    // ---- P2 (regs = v bits 4..7): stages 4..7, then store from registers ----
#pragma unroll
    for (int i = 0; i < 16; i++) r[i] = S[sw3(vQ2(t, (unsigned)i))];
    group4<0xF>(r, CB + 4, SB + 4);

#pragma unroll
    for (int i = 0; i < 16; i++) {
        const unsigned g = gmap<HIGH>(blk, vQ2(t, (unsigned)i));
        if (OUT_REAL) {
            __stcs(outp + g, r[i].x);                      // real plane, no reuse
            if (write_imag) outp[g + NSTATES] = r[i].y;
        } else {
            dst[g] = r[i];                                 // keep in L2 for next pass
        }
    }
}

extern "C" void kernel_launch(void* const* d_in, const int* in_sizes, int n_in,
                              void* d_out, int out_size) {
    if (n_in < 3) return;
    // Binding (proven round 9): params = smallest input; remaining two in
    // original order are state_real, state_imag. Never index past n_in.
    int pi = 0;
    for (int i = 1; i < n_in && i < 8; i++)
        if (in_sizes[i] < in_sizes[pi]) pi = i;
    int si0 = -1, si1 = -1;
    for (int i = 0; i < n_in && i < 8; i++) {
        if (i == pi) continue;
        if (si0 < 0) si0 = i; else if (si1 < 0) si1 = i;
    }
    if (si0 < 0 || si1 < 0) return;
    if ((unsigned)in_sizes[si0] < NSTATES || (unsigned)in_sizes[si1] < NSTATES)
        return;
    // Output contract (proven rounds 9/11/12): out_size = NSTATES float32
    // components = the REAL parts of the final state.
    if ((unsigned)out_size < NSTATES) return;
    const int write_imag = ((long long)out_size >= 2LL * NSTATES) ? 1 : 0;

    const float* params = (const float*)d_in[pi];
    const float* sre    = (const float*)d_in[si0];
    const float* sim    = (const float*)d_in[si1];
    float*       out    = (float*)d_out;

    const dim3 grid(1024), block(256);

    // Non-gather passes are block-local identity maps -> safe IN-PLACE
    // (each location read and written only by its owning block). Keeps the
    // live working set (A+B <= 64MB) L2-resident.
    // L0: LOW planar->A, then HIGH in-place on A.
    vqc_pass16<false, false, true,  false><<<grid, block>>>(sre, sim, nullptr, 0, 0, 1, params, 0);
    vqc_pass16<true,  false, false, false><<<grid, block>>>(nullptr, nullptr, nullptr, 0, 1, 1, params, 12);
    // L1: LOW with gathered CNOT-chain perm A->B, then HIGH in-place on B.
    vqc_pass16<false, true,  false, false><<<grid, block>>>(nullptr, nullptr, nullptr, 0, 1, 2, params, 22);
    vqc_pass16<true,  false, false, false><<<grid, block>>>(nullptr, nullptr, nullptr, 0, 2, 2, params, 34);
    // L2 (stages commute): HIGH with gathered perm B->A, then LOW A->out (real).
    vqc_pass16<true,  true,  false, false><<<grid, block>>>(nullptr, nullptr, nullptr, 0, 2, 1, params, 56);
    vqc_pass16<false, false, false, true ><<<grid, block>>>(nullptr, nullptr, out, write_imag, 1, 0, params, 44);
}